// round 14
// baseline (speedup 1.0000x reference)
#include <cuda_runtime.h>
#include <cuda_fp16.h>
#include <cstdint>

#define BB 2
#define CC 128
#define NN 4096
#define NSS 2048
#define HH 4
#define DD 32

// device scratch (no cudaMalloc allowed)
__device__ int      g_inv[BB*NN];        // inverse permutation: n -> source j
__device__ float    g_Qf[BB*CC*NN];      // Q fp32 [b][h*32+d][n], pre-scaled
__device__ uint32_t g_Kt[BB*CC*NN/2];    // K fp16 [b][h][n][dpair]  (transposed)
__device__ uint32_t g_Vb[BB*CC*NN/2];    // V fp16 [b][h*32+d][n] (n-pairs packed)

// ---------------------------------------------------------------------------
// PTX helpers
// ---------------------------------------------------------------------------
__device__ __forceinline__ uint32_t f2tf32(float x) {
    uint32_t u; asm("cvt.rna.tf32.f32 %0, %1;" : "=r"(u) : "f"(x)); return u;
}
__device__ __forceinline__ float tf32f(float x) {
    return __uint_as_float(f2tf32(x));
}
__device__ __forceinline__ uint32_t packh(float lo, float hi) {
    uint32_t u; asm("cvt.rn.f16x2.f32 %0, %1, %2;" : "=r"(u) : "f"(hi), "f"(lo)); return u;
}
__device__ __forceinline__ uint32_t ex2h(uint32_t x) {
    uint32_t y; asm("ex2.approx.f16x2 %0, %1;" : "=r"(y) : "r"(x)); return y;
}
__device__ __forceinline__ uint32_t hadd2(uint32_t a, uint32_t b) {
    uint32_t r; asm("add.f16x2 %0, %1, %2;" : "=r"(r) : "r"(a), "r"(b)); return r;
}
__device__ __forceinline__ uint32_t smem_u32p(const void* p) {
    uint32_t a;
    asm("{ .reg .u64 t; cvta.to.shared.u64 t, %1; cvt.u32.u64 %0, t; }" : "=r"(a) : "l"(p));
    return a;
}
__device__ __forceinline__ void ldsm_x4(uint32_t& r0, uint32_t& r1, uint32_t& r2,
                                        uint32_t& r3, uint32_t addr) {
    asm volatile("ldmatrix.sync.aligned.m8n8.x4.shared.b16 {%0,%1,%2,%3}, [%4];"
        : "=r"(r0), "=r"(r1), "=r"(r2), "=r"(r3) : "r"(addr));
}
__device__ __forceinline__ void mma_tf32_k8(float c[4], const uint32_t a[4],
                                            uint32_t b0, uint32_t b1) {
    asm volatile(
        "mma.sync.aligned.m16n8k8.row.col.f32.tf32.tf32.f32 "
        "{%0,%1,%2,%3}, {%4,%5,%6,%7}, {%8,%9}, {%0,%1,%2,%3};"
        : "+f"(c[0]), "+f"(c[1]), "+f"(c[2]), "+f"(c[3])
        : "r"(a[0]), "r"(a[1]), "r"(a[2]), "r"(a[3]), "r"(b0), "r"(b1));
}
__device__ __forceinline__ void mma_f16_k16(float c[4], const uint32_t a[4],
                                            uint32_t b0, uint32_t b1) {
    asm volatile(
        "mma.sync.aligned.m16n8k16.row.col.f32.f16.f16.f32 "
        "{%0,%1,%2,%3}, {%4,%5,%6,%7}, {%8,%9}, {%0,%1,%2,%3};"
        : "+f"(c[0]), "+f"(c[1]), "+f"(c[2]), "+f"(c[3])
        : "r"(a[0]), "r"(a[1]), "r"(a[2]), "r"(a[3]), "r"(b0), "r"(b1));
}

// ---------------------------------------------------------------------------
// prep: build inverse permutation only (no data movement).
// t < BB*NSS -> sel entries (j), else drop entries (NSS + j).
// ---------------------------------------------------------------------------
__global__ void prep_kernel(const void* __restrict__ idx_sel, const void* __restrict__ idx_drop)
{
    int t = blockIdx.x * 256 + threadIdx.x;    // 0 .. 2*BB*NSS-1
    int which = (t >= BB*NSS) ? 1 : 0;
    int u = t - which * (BB*NSS);
    int b = u / NSS, j = u % NSS;
    const int* is = (const int*)idx_sel;
    bool is64 = (is[1] == 0) & (is[3] == 0) & (is[5] == 0) & (is[7] == 0);
    const void* idx = which ? idx_drop : idx_sel;
    int col = is64 ? (int)((const long long*)idx)[b*NSS + j]
                   : ((const int*)idx)[b*NSS + j];
    g_inv[b*NN + col] = j + which * NSS;
}

// ---------------------------------------------------------------------------
// projection: Q,K,V single-pass tf32 (X gathered from sel/drop via g_inv;
// K emitted fp16 transposed [n][dpair], V fp16 [d][npair]); skip split tf32.
// ---------------------------------------------------------------------------
#define XST 68
#define WST 36
#define PSMEM (2*128*XST*4 + 2*128*WST*4)   // 106496 bytes

__global__ __launch_bounds__(256) void proj_kernel(
    const float* __restrict__ pcd_up,
    const float* __restrict__ sel, const float* __restrict__ drop,
    const float* __restrict__ Wq, const float* __restrict__ Wk,
    const float* __restrict__ Wv, const float* __restrict__ Wsk,
    float* __restrict__ out)
{
    extern __shared__ __align__(16) float psm[];
    float* Xh = psm;                 // [128][XST]
    float* Xl = psm + 128*XST;       // [128][XST]
    float* Wh = psm + 2*128*XST;     // [128][WST]
    float* Wl = Wh + 128*WST;        // [128][WST]

    int tid = threadIdx.x;
    int w = tid >> 5, lane = tid & 31, gid = lane >> 2, tig = lane & 3;
    int n0 = blockIdx.x * 64;
    int b  = blockIdx.y;
    int m0 = w * 16;

    int wm[4], wk4[4];
    #pragma unroll
    for (int r = 0; r < 4; r++) {
        int i = r*256 + tid;
        wm[r] = i >> 3; wk4[r] = (i & 7) << 2;
    }

    const float QSCALE = 0.17677669529663687f * 1.4426950408889634f;

    // stage X by gathering scattered source values via inverse permutation
    {
        const int* inv = g_inv + b*NN + n0;
        const float* selb = sel + (size_t)b*CC*NSS;
        const float* dropb = drop + (size_t)b*CC*NSS;
        #pragma unroll
        for (int i = tid; i < 2048; i += 256) {
            int r = i >> 4, c4 = (i & 15) << 2;
            #pragma unroll
            for (int u = 0; u < 4; u++) {
                int jj = inv[c4 + u];
                float v = (jj < NSS) ? selb[r*NSS + jj] : dropb[r*NSS + jj - NSS];
                Xh[r*XST + c4 + u] = tf32f(v);
            }
        }
    }

    for (int p = 0; p < 3; p++) {
        const float* Wp = (p == 0) ? Wq : (p == 1) ? Wk : Wv;
        float acc[8][4];
        #pragma unroll
        for (int i = 0; i < 8; i++)
            #pragma unroll
            for (int j = 0; j < 4; j++) acc[i][j] = 0.f;

        float4 wreg[4];
        #pragma unroll
        for (int r = 0; r < 4; r++)
            wreg[r] = *(const float4*)&Wp[wm[r]*CC + wk4[r]];

        for (int kc = 0; kc < 4; kc++) {
            __syncthreads();
            #pragma unroll
            for (int r = 0; r < 4; r++) {
                Wh[wm[r]*WST + wk4[r] + 0] = tf32f(wreg[r].x);
                Wh[wm[r]*WST + wk4[r] + 1] = tf32f(wreg[r].y);
                Wh[wm[r]*WST + wk4[r] + 2] = tf32f(wreg[r].z);
                Wh[wm[r]*WST + wk4[r] + 3] = tf32f(wreg[r].w);
            }
            __syncthreads();
            if (kc < 3) {
                #pragma unroll
                for (int r = 0; r < 4; r++)
                    wreg[r] = *(const float4*)&Wp[wm[r]*CC + (kc + 1)*32 + wk4[r]];
            }
            #pragma unroll
            for (int ks = 0; ks < 4; ks++) {
                int kk = ks * 8;
                uint32_t a[4];
                a[0] = __float_as_uint(Wh[(m0 + gid    )*WST + kk + tig    ]);
                a[1] = __float_as_uint(Wh[(m0 + gid + 8)*WST + kk + tig    ]);
                a[2] = __float_as_uint(Wh[(m0 + gid    )*WST + kk + tig + 4]);
                a[3] = __float_as_uint(Wh[(m0 + gid + 8)*WST + kk + tig + 4]);
                #pragma unroll
                for (int nt = 0; nt < 8; nt++) {
                    uint32_t b0 = __float_as_uint(Xh[(kc*32 + kk + tig    )*XST + nt*8 + gid]);
                    uint32_t b1 = __float_as_uint(Xh[(kc*32 + kk + tig + 4)*XST + nt*8 + gid]);
                    mma_tf32_k8(acc[nt], a, b0, b1);
                }
            }
        }
        if (p == 0) {
            float* q = g_Qf + (size_t)(b*CC)*NN;
            #pragma unroll
            for (int nt = 0; nt < 8; nt++) {
                int n = n0 + nt*8 + 2*tig;
                *(float2*)&q[(m0 + gid    )*NN + n] = make_float2(acc[nt][0]*QSCALE, acc[nt][1]*QSCALE);
                *(float2*)&q[(m0 + gid + 8)*NN + n] = make_float2(acc[nt][2]*QSCALE, acc[nt][3]*QSCALE);
            }
        } else if (p == 1) {
            // K transposed: [b][h][n][dhalf], h = w>>1, dh = (w&1)*16 + gid
            __half* kt = (__half*)g_Kt;
            size_t kb = ((size_t)(b*HH + (w >> 1))) * NN;
            int dh = (w & 1)*16 + gid;
            #pragma unroll
            for (int nt = 0; nt < 8; nt++) {
                int n = n0 + nt*8 + 2*tig;
                kt[(kb + n    )*32 + dh    ] = __float2half(acc[nt][0]);
                kt[(kb + n + 1)*32 + dh    ] = __float2half(acc[nt][1]);
                kt[(kb + n    )*32 + dh + 8] = __float2half(acc[nt][2]);
                kt[(kb + n + 1)*32 + dh + 8] = __float2half(acc[nt][3]);
            }
        } else {
            uint32_t* dst = g_Vb + (size_t)(b*CC)*(NN/2);
            #pragma unroll
            for (int nt = 0; nt < 8; nt++) {
                int np = (n0 + nt*8) / 2 + tig;
                dst[(m0 + gid    )*(NN/2) + np] = packh(acc[nt][0], acc[nt][1]);
                dst[(m0 + gid + 8)*(NN/2) + np] = packh(acc[nt][2], acc[nt][3]);
            }
        }
    }

    // ---- skip pass: split tf32 (fp32-accurate), X from pcd_up ----
    __syncthreads();
    {
        const float* xs = pcd_up + b*CC*NN;
        #pragma unroll
        for (int i = tid; i < 2048; i += 256) {
            int r = i >> 4, c4 = (i & 15) << 2;
            float4 v = *(const float4*)&xs[r*NN + n0 + c4];
            float h0 = tf32f(v.x), h1 = tf32f(v.y), h2 = tf32f(v.z), h3 = tf32f(v.w);
            Xh[r*XST + c4 + 0] = h0;  Xl[r*XST + c4 + 0] = tf32f(v.x - h0);
            Xh[r*XST + c4 + 1] = h1;  Xl[r*XST + c4 + 1] = tf32f(v.y - h1);
            Xh[r*XST + c4 + 2] = h2;  Xl[r*XST + c4 + 2] = tf32f(v.z - h2);
            Xh[r*XST + c4 + 3] = h3;  Xl[r*XST + c4 + 3] = tf32f(v.w - h3);
        }
    }

    float acc[8][4];
    #pragma unroll
    for (int i = 0; i < 8; i++)
        #pragma unroll
        for (int j = 0; j < 4; j++) acc[i][j] = 0.f;

    float4 wreg[4];
    #pragma unroll
    for (int r = 0; r < 4; r++)
        wreg[r] = *(const float4*)&Wsk[wm[r]*CC + wk4[r]];

    for (int kc = 0; kc < 4; kc++) {
        __syncthreads();
        #pragma unroll
        for (int r = 0; r < 4; r++) {
            float h0 = tf32f(wreg[r].x), h1 = tf32f(wreg[r].y);
            float h2 = tf32f(wreg[r].z), h3 = tf32f(wreg[r].w);
            Wh[wm[r]*WST + wk4[r] + 0] = h0;  Wl[wm[r]*WST + wk4[r] + 0] = tf32f(wreg[r].x - h0);
            Wh[wm[r]*WST + wk4[r] + 1] = h1;  Wl[wm[r]*WST + wk4[r] + 1] = tf32f(wreg[r].y - h1);
            Wh[wm[r]*WST + wk4[r] + 2] = h2;  Wl[wm[r]*WST + wk4[r] + 2] = tf32f(wreg[r].z - h2);
            Wh[wm[r]*WST + wk4[r] + 3] = h3;  Wl[wm[r]*WST + wk4[r] + 3] = tf32f(wreg[r].w - h3);
        }
        __syncthreads();
        if (kc < 3) {
            #pragma unroll
            for (int r = 0; r < 4; r++)
                wreg[r] = *(const float4*)&Wsk[wm[r]*CC + (kc + 1)*32 + wk4[r]];
        }
        #pragma unroll
        for (int ks = 0; ks < 4; ks++) {
            int kk = ks * 8;
            uint32_t ah[4], al[4];
            ah[0] = __float_as_uint(Wh[(m0 + gid    )*WST + kk + tig    ]);
            ah[1] = __float_as_uint(Wh[(m0 + gid + 8)*WST + kk + tig    ]);
            ah[2] = __float_as_uint(Wh[(m0 + gid    )*WST + kk + tig + 4]);
            ah[3] = __float_as_uint(Wh[(m0 + gid + 8)*WST + kk + tig + 4]);
            al[0] = __float_as_uint(Wl[(m0 + gid    )*WST + kk + tig    ]);
            al[1] = __float_as_uint(Wl[(m0 + gid + 8)*WST + kk + tig    ]);
            al[2] = __float_as_uint(Wl[(m0 + gid    )*WST + kk + tig + 4]);
            al[3] = __float_as_uint(Wl[(m0 + gid + 8)*WST + kk + tig + 4]);
            #pragma unroll
            for (int nt = 0; nt < 8; nt++) {
                uint32_t bh0 = __float_as_uint(Xh[(kc*32 + kk + tig    )*XST + nt*8 + gid]);
                uint32_t bh1 = __float_as_uint(Xh[(kc*32 + kk + tig + 4)*XST + nt*8 + gid]);
                uint32_t bl0 = __float_as_uint(Xl[(kc*32 + kk + tig    )*XST + nt*8 + gid]);
                uint32_t bl1 = __float_as_uint(Xl[(kc*32 + kk + tig + 4)*XST + nt*8 + gid]);
                mma_tf32_k8(acc[nt], ah, bh0, bh1);
                mma_tf32_k8(acc[nt], ah, bl0, bl1);
                mma_tf32_k8(acc[nt], al, bh0, bh1);
            }
        }
    }
    #pragma unroll
    for (int nt = 0; nt < 8; nt++) {
        int n = n0 + nt*8 + 2*tig;
        float* o = out + (size_t)(b*CC)*NN;
        *(float2*)&o[(m0 + gid    )*NN + n] = make_float2(acc[nt][0], acc[nt][1]);
        *(float2*)&o[(m0 + gid + 8)*NN + n] = make_float2(acc[nt][2], acc[nt][3]);
    }
}

// ---------------------------------------------------------------------------
// flash attention, fp16 m16n8k16, 512 threads (16 warps, 16 q-rows each) for
// 4 warps/SMSP latency hiding. 256 q per CTA, grid 128 (1 CTA/SM).
// Double-buffered K/V smem, one barrier/kt. lsum via HADD2.
// ---------------------------------------------------------------------------
#define KPST 20    // u32 stride (80B rows): LDSM conflict-free
#define VPST 36    // u32 stride (144B rows)
#define KBUF (64*KPST)
#define VBUF (32*VPST)

__global__ __launch_bounds__(512, 1) void flash_kernel(float* __restrict__ out)
{
    __shared__ __align__(16) uint32_t Kp[2*KBUF];    // [buf][key][dpair]
    __shared__ __align__(16) uint32_t Vp[2*VBUF];    // [buf][d][jpair]

    int tid = threadIdx.x;
    int w = tid >> 5, lane = tid & 31, gid = lane >> 2, tig = lane & 3;
    int qt = blockIdx.x, h = blockIdx.y, b = blockIdx.z;
    int q0 = qt * 256;
    int r0 = w*16 + gid;

    const float*    Qf = g_Qf + (size_t)(b*CC + h*32)*NN + q0;
    const uint32_t* Kt = g_Kt + ((size_t)(b*HH + h)*NN)*16;
    const uint32_t* Vu = g_Vb + (size_t)(b*CC + h*32)*(NN/2);

    // staging: K 8B/thread, V 2x4B/thread (512 threads)
    int skey = tid >> 3, sq = tid & 7;            // K: key row, 8B chunk
    int svd  = tid >> 4, svq = tid & 15;          // V: d row, cols svq, svq+16

    // ldmatrix per-thread base addresses (buffer 0)
    int lrow = lane & 7, lm = lane >> 3;
    uint32_t kp_b = smem_u32p(Kp), vp_b = smem_u32p(Vp);
    uint32_t kaddr0 = kp_b + (uint32_t)(lrow*(KPST*4) + (lm >> 1)*32 + (lm & 1)*16);
    uint32_t vaddr0 = vp_b + (uint32_t)(((lm >> 1)*8 + lrow)*(VPST*4) + (lm & 1)*16);

    // Q fragments (fp16, persist all tiles)
    uint32_t qa[2][4];
    #pragma unroll
    for (int ks = 0; ks < 2; ks++) {
        int d = ks*16 + 2*tig;
        qa[ks][0] = packh(Qf[(d    )*NN + r0    ], Qf[(d + 1)*NN + r0    ]);
        qa[ks][1] = packh(Qf[(d    )*NN + r0 + 8], Qf[(d + 1)*NN + r0 + 8]);
        qa[ks][2] = packh(Qf[(d + 8)*NN + r0    ], Qf[(d + 9)*NN + r0    ]);
        qa[ks][3] = packh(Qf[(d + 8)*NN + r0 + 8], Qf[(d + 9)*NN + r0 + 8]);
    }

    float o[4][4];
    #pragma unroll
    for (int i = 0; i < 4; i++)
        #pragma unroll
        for (int j = 0; j < 4; j++) o[i][j] = 0.f;
    float lsum0 = 0.f, lsum1 = 0.f;

    // stage tile 0 into buffer 0
    {
        uint2 kv = *(const uint2*)&Kt[(size_t)skey*16 + sq*2];
        *(uint2*)&Kp[skey*KPST + sq*2] = kv;
        Vp[svd*VPST + svq     ] = Vu[(size_t)svd*(NN/2) + svq     ];
        Vp[svd*VPST + svq + 16] = Vu[(size_t)svd*(NN/2) + svq + 16];
    }
    __syncthreads();

    for (int kt = 0; kt < 64; kt++) {
        int cur = kt & 1, nxt = cur ^ 1;
        uint32_t kaddr = kaddr0 + (uint32_t)(cur * (KBUF*4));
        uint32_t vaddr = vaddr0 + (uint32_t)(cur * (VBUF*4));

        // prefetch next tile into registers
        uint2 nK; uint32_t nv0, nv1;
        if (kt < 63) {
            nK  = *(const uint2*)&Kt[(size_t)((kt + 1)*64 + skey)*16 + sq*2];
            nv0 = Vu[(size_t)svd*(NN/2) + (kt + 1)*32 + svq     ];
            nv1 = Vu[(size_t)svd*(NN/2) + (kt + 1)*32 + svq + 16];
        }

        // S = Q @ K^T per n-tile; ex2 -> PV A-fragments; HADD2 row sums
        uint32_t pa[4][4];
        uint32_t hs0 = 0u, hs1 = 0u;
        #pragma unroll
        for (int nt = 0; nt < 8; nt++) {
            uint32_t k0, k1, k2, k3;
            ldsm_x4(k0, k1, k2, k3, kaddr + (uint32_t)(nt*8*KPST*4));
            float sv[4] = {0.f, 0.f, 0.f, 0.f};
            mma_f16_k16(sv, qa[0], k0, k1);
            mma_f16_k16(sv, qa[1], k2, k3);
            uint32_t p01 = ex2h(packh(sv[0], sv[1]));
            uint32_t p23 = ex2h(packh(sv[2], sv[3]));
            hs0 = hadd2(hs0, p01);
            hs1 = hadd2(hs1, p23);
            pa[nt >> 1][(nt & 1)*2    ] = p01;
            pa[nt >> 1][(nt & 1)*2 + 1] = p23;
        }
        {
            float2 t0 = __half22float2(*(const __half2*)&hs0);
            float2 t1 = __half22float2(*(const __half2*)&hs1);
            lsum0 += t0.x + t0.y;
            lsum1 += t1.x + t1.y;
        }

        // O += P @ V
        #pragma unroll
        for (int g = 0; g < 4; g++) {
            uint32_t vb0[4], vb1[4];
            ldsm_x4(vb0[0], vb0[1], vb0[2], vb0[3], vaddr + (uint32_t)(g*32));
            ldsm_x4(vb1[0], vb1[1], vb1[2], vb1[3], vaddr + (uint32_t)(16*VPST*4 + g*32));
            mma_f16_k16(o[0], pa[g], vb0[0], vb0[1]);
            mma_f16_k16(o[1], pa[g], vb0[2], vb0[3]);
            mma_f16_k16(o[2], pa[g], vb1[0], vb1[1]);
            mma_f16_k16(o[3], pa[g], vb1[2], vb1[3]);
        }

        // store prefetched tile into the OTHER buffer; single barrier per kt
        if (kt < 63) {
            *(uint2*)&Kp[nxt*KBUF + skey*KPST + sq*2] = nK;
            Vp[nxt*VBUF + svd*VPST + svq     ] = nv0;
            Vp[nxt*VBUF + svd*VPST + svq + 16] = nv1;
            __syncthreads();
        }
    }

    // epilogue: reduce lsum across row group, divide, add into out
    lsum0 += __shfl_xor_sync(0xffffffffu, lsum0, 1);
    lsum0 += __shfl_xor_sync(0xffffffffu, lsum0, 2);
    lsum1 += __shfl_xor_sync(0xffffffffu, lsum1, 1);
    lsum1 += __shfl_xor_sync(0xffffffffu, lsum1, 2);
    float inv0 = 1.f / lsum0, inv1 = 1.f / lsum1;
    #pragma unroll
    for (int nt = 0; nt < 4; nt++) {
        int d = nt*8 + 2*tig;
        float* base = out + (size_t)(b*CC + h*32)*NN + q0;
        base[(d    )*NN + r0    ] += o[nt][0] * inv0;
        base[(d + 1)*NN + r0    ] += o[nt][1] * inv0;
        base[(d    )*NN + r0 + 8] += o[nt][2] * inv1;
        base[(d + 1)*NN + r0 + 8] += o[nt][3] * inv1;
    }
}

extern "C" void kernel_launch(void* const* d_in, const int* in_sizes, int n_in,
                              void* d_out, int out_size)
{
    const float* pcd_up = (const float*)d_in[0];
    const float* sel    = (const float*)d_in[1];
    const float* drop   = (const float*)d_in[2];
    // d_in[3] = pcd_up_xyz, unused by the reference math
    const float* Wq     = (const float*)d_in[4];
    const float* Wk     = (const float*)d_in[5];
    const float* Wv     = (const float*)d_in[6];
    const float* Wsk    = (const float*)d_in[7];
    const void*  idxs   = d_in[8];
    const void*  idxd   = d_in[9];
    float* out = (float*)d_out;

    static bool attr_set = false;
    if (!attr_set) {
        cudaFuncSetAttribute(proj_kernel, cudaFuncAttributeMaxDynamicSharedMemorySize,
                             PSMEM);
        attr_set = true;
    }

    prep_kernel<<<(2*BB*NSS)/256, 256>>>(idxs, idxd);
    proj_kernel<<<dim3(NN/64, BB), 256, PSMEM>>>(pcd_up, sel, drop, Wq, Wk, Wv, Wsk, out);
    flash_kernel<<<dim3(NN/256, HH, BB), 512>>>(out);
}

// round 15
// speedup vs baseline: 1.1550x; 1.1550x over previous
#include <cuda_runtime.h>
#include <cuda_fp16.h>
#include <cstdint>

#define BB 2
#define CC 128
#define NN 4096
#define NSS 2048
#define HH 4
#define DD 32

// device scratch (no cudaMalloc allowed)
__device__ int      g_inv[BB*NN];        // inverse permutation: n -> source j
__device__ float    g_Qf[BB*CC*NN];      // Q fp32 [b][h*32+d][n], pre-scaled
__device__ uint32_t g_Kt[BB*CC*NN/2];    // K fp16 [b][h][n][dpair]  (transposed)
__device__ uint32_t g_Vb[BB*CC*NN/2];    // V fp16 [b][h*32+d][n] (n-pairs packed)

// ---------------------------------------------------------------------------
// PTX helpers
// ---------------------------------------------------------------------------
__device__ __forceinline__ uint32_t f2tf32(float x) {
    uint32_t u; asm("cvt.rna.tf32.f32 %0, %1;" : "=r"(u) : "f"(x)); return u;
}
__device__ __forceinline__ float tf32f(float x) {
    return __uint_as_float(f2tf32(x));
}
__device__ __forceinline__ uint32_t packh(float lo, float hi) {
    uint32_t u; asm("cvt.rn.f16x2.f32 %0, %1, %2;" : "=r"(u) : "f"(hi), "f"(lo)); return u;
}
__device__ __forceinline__ uint32_t ex2h(uint32_t x) {
    uint32_t y; asm("ex2.approx.f16x2 %0, %1;" : "=r"(y) : "r"(x)); return y;
}
__device__ __forceinline__ uint32_t hadd2(uint32_t a, uint32_t b) {
    uint32_t r; asm("add.f16x2 %0, %1, %2;" : "=r"(r) : "r"(a), "r"(b)); return r;
}
__device__ __forceinline__ uint32_t smem_u32p(const void* p) {
    uint32_t a;
    asm("{ .reg .u64 t; cvta.to.shared.u64 t, %1; cvt.u32.u64 %0, t; }" : "=r"(a) : "l"(p));
    return a;
}
__device__ __forceinline__ void ldsm_x4(uint32_t& r0, uint32_t& r1, uint32_t& r2,
                                        uint32_t& r3, uint32_t addr) {
    asm volatile("ldmatrix.sync.aligned.m8n8.x4.shared.b16 {%0,%1,%2,%3}, [%4];"
        : "=r"(r0), "=r"(r1), "=r"(r2), "=r"(r3) : "r"(addr));
}
__device__ __forceinline__ void mma_tf32_k8(float c[4], const uint32_t a[4],
                                            uint32_t b0, uint32_t b1) {
    asm volatile(
        "mma.sync.aligned.m16n8k8.row.col.f32.tf32.tf32.f32 "
        "{%0,%1,%2,%3}, {%4,%5,%6,%7}, {%8,%9}, {%0,%1,%2,%3};"
        : "+f"(c[0]), "+f"(c[1]), "+f"(c[2]), "+f"(c[3])
        : "r"(a[0]), "r"(a[1]), "r"(a[2]), "r"(a[3]), "r"(b0), "r"(b1));
}
__device__ __forceinline__ void mma_f16_k16(float c[4], const uint32_t a[4],
                                            uint32_t b0, uint32_t b1) {
    asm volatile(
        "mma.sync.aligned.m16n8k16.row.col.f32.f16.f16.f32 "
        "{%0,%1,%2,%3}, {%4,%5,%6,%7}, {%8,%9}, {%0,%1,%2,%3};"
        : "+f"(c[0]), "+f"(c[1]), "+f"(c[2]), "+f"(c[3])
        : "r"(a[0]), "r"(a[1]), "r"(a[2]), "r"(a[3]), "r"(b0), "r"(b1));
}

// ---------------------------------------------------------------------------
// prep: build inverse permutation only (no data movement).
// ---------------------------------------------------------------------------
__global__ void prep_kernel(const void* __restrict__ idx_sel, const void* __restrict__ idx_drop)
{
    int t = blockIdx.x * 256 + threadIdx.x;    // 0 .. 2*BB*NSS-1
    int which = (t >= BB*NSS) ? 1 : 0;
    int u = t - which * (BB*NSS);
    int b = u / NSS, j = u % NSS;
    const int* is = (const int*)idx_sel;
    bool is64 = (is[1] == 0) & (is[3] == 0) & (is[5] == 0) & (is[7] == 0);
    const void* idx = which ? idx_drop : idx_sel;
    int col = is64 ? (int)((const long long*)idx)[b*NSS + j]
                   : ((const int*)idx)[b*NSS + j];
    g_inv[b*NN + col] = j + which * NSS;
}

// ---------------------------------------------------------------------------
// projection: Q,K,V single-pass tf32 (X gathered from sel/drop via g_inv;
// K emitted fp16 transposed [n][dpair], V fp16 [d][npair]); skip split tf32.
// ---------------------------------------------------------------------------
#define XST 68
#define WST 36
#define PSMEM (2*128*XST*4 + 2*128*WST*4)   // 106496 bytes

__global__ __launch_bounds__(256) void proj_kernel(
    const float* __restrict__ pcd_up,
    const float* __restrict__ sel, const float* __restrict__ drop,
    const float* __restrict__ Wq, const float* __restrict__ Wk,
    const float* __restrict__ Wv, const float* __restrict__ Wsk,
    float* __restrict__ out)
{
    extern __shared__ __align__(16) float psm[];
    float* Xh = psm;                 // [128][XST]
    float* Xl = psm + 128*XST;       // [128][XST]
    float* Wh = psm + 2*128*XST;     // [128][WST]
    float* Wl = Wh + 128*WST;        // [128][WST]

    int tid = threadIdx.x;
    int w = tid >> 5, lane = tid & 31, gid = lane >> 2, tig = lane & 3;
    int n0 = blockIdx.x * 64;
    int b  = blockIdx.y;
    int m0 = w * 16;

    int wm[4], wk4[4];
    #pragma unroll
    for (int r = 0; r < 4; r++) {
        int i = r*256 + tid;
        wm[r] = i >> 3; wk4[r] = (i & 7) << 2;
    }

    const float QSCALE = 0.17677669529663687f * 1.4426950408889634f;

    // stage X by gathering scattered source values via inverse permutation
    {
        const int* inv = g_inv + b*NN + n0;
        const float* selb = sel + (size_t)b*CC*NSS;
        const float* dropb = drop + (size_t)b*CC*NSS;
        #pragma unroll
        for (int i = tid; i < 2048; i += 256) {
            int r = i >> 4, c4 = (i & 15) << 2;
            #pragma unroll
            for (int u = 0; u < 4; u++) {
                int jj = inv[c4 + u];
                float v = (jj < NSS) ? selb[r*NSS + jj] : dropb[r*NSS + jj - NSS];
                Xh[r*XST + c4 + u] = tf32f(v);
            }
        }
    }

    for (int p = 0; p < 3; p++) {
        const float* Wp = (p == 0) ? Wq : (p == 1) ? Wk : Wv;
        float acc[8][4];
        #pragma unroll
        for (int i = 0; i < 8; i++)
            #pragma unroll
            for (int j = 0; j < 4; j++) acc[i][j] = 0.f;

        float4 wreg[4];
        #pragma unroll
        for (int r = 0; r < 4; r++)
            wreg[r] = *(const float4*)&Wp[wm[r]*CC + wk4[r]];

        for (int kc = 0; kc < 4; kc++) {
            __syncthreads();
            #pragma unroll
            for (int r = 0; r < 4; r++) {
                Wh[wm[r]*WST + wk4[r] + 0] = tf32f(wreg[r].x);
                Wh[wm[r]*WST + wk4[r] + 1] = tf32f(wreg[r].y);
                Wh[wm[r]*WST + wk4[r] + 2] = tf32f(wreg[r].z);
                Wh[wm[r]*WST + wk4[r] + 3] = tf32f(wreg[r].w);
            }
            __syncthreads();
            if (kc < 3) {
                #pragma unroll
                for (int r = 0; r < 4; r++)
                    wreg[r] = *(const float4*)&Wp[wm[r]*CC + (kc + 1)*32 + wk4[r]];
            }
            #pragma unroll
            for (int ks = 0; ks < 4; ks++) {
                int kk = ks * 8;
                uint32_t a[4];
                a[0] = __float_as_uint(Wh[(m0 + gid    )*WST + kk + tig    ]);
                a[1] = __float_as_uint(Wh[(m0 + gid + 8)*WST + kk + tig    ]);
                a[2] = __float_as_uint(Wh[(m0 + gid    )*WST + kk + tig + 4]);
                a[3] = __float_as_uint(Wh[(m0 + gid + 8)*WST + kk + tig + 4]);
                #pragma unroll
                for (int nt = 0; nt < 8; nt++) {
                    uint32_t b0 = __float_as_uint(Xh[(kc*32 + kk + tig    )*XST + nt*8 + gid]);
                    uint32_t b1 = __float_as_uint(Xh[(kc*32 + kk + tig + 4)*XST + nt*8 + gid]);
                    mma_tf32_k8(acc[nt], a, b0, b1);
                }
            }
        }
        if (p == 0) {
            float* q = g_Qf + (size_t)(b*CC)*NN;
            #pragma unroll
            for (int nt = 0; nt < 8; nt++) {
                int n = n0 + nt*8 + 2*tig;
                *(float2*)&q[(m0 + gid    )*NN + n] = make_float2(acc[nt][0]*QSCALE, acc[nt][1]*QSCALE);
                *(float2*)&q[(m0 + gid + 8)*NN + n] = make_float2(acc[nt][2]*QSCALE, acc[nt][3]*QSCALE);
            }
        } else if (p == 1) {
            // K transposed: [b][h][n][dhalf], h = w>>1, dh = (w&1)*16 + gid
            __half* kt = (__half*)g_Kt;
            size_t kb = ((size_t)(b*HH + (w >> 1))) * NN;
            int dh = (w & 1)*16 + gid;
            #pragma unroll
            for (int nt = 0; nt < 8; nt++) {
                int n = n0 + nt*8 + 2*tig;
                kt[(kb + n    )*32 + dh    ] = __float2half(acc[nt][0]);
                kt[(kb + n + 1)*32 + dh    ] = __float2half(acc[nt][1]);
                kt[(kb + n    )*32 + dh + 8] = __float2half(acc[nt][2]);
                kt[(kb + n + 1)*32 + dh + 8] = __float2half(acc[nt][3]);
            }
        } else {
            uint32_t* dst = g_Vb + (size_t)(b*CC)*(NN/2);
            #pragma unroll
            for (int nt = 0; nt < 8; nt++) {
                int np = (n0 + nt*8) / 2 + tig;
                dst[(m0 + gid    )*(NN/2) + np] = packh(acc[nt][0], acc[nt][1]);
                dst[(m0 + gid + 8)*(NN/2) + np] = packh(acc[nt][2], acc[nt][3]);
            }
        }
    }

    // ---- skip pass: split tf32 (fp32-accurate), X from pcd_up ----
    __syncthreads();
    {
        const float* xs = pcd_up + b*CC*NN;
        #pragma unroll
        for (int i = tid; i < 2048; i += 256) {
            int r = i >> 4, c4 = (i & 15) << 2;
            float4 v = *(const float4*)&xs[r*NN + n0 + c4];
            float h0 = tf32f(v.x), h1 = tf32f(v.y), h2 = tf32f(v.z), h3 = tf32f(v.w);
            Xh[r*XST + c4 + 0] = h0;  Xl[r*XST + c4 + 0] = tf32f(v.x - h0);
            Xh[r*XST + c4 + 1] = h1;  Xl[r*XST + c4 + 1] = tf32f(v.y - h1);
            Xh[r*XST + c4 + 2] = h2;  Xl[r*XST + c4 + 2] = tf32f(v.z - h2);
            Xh[r*XST + c4 + 3] = h3;  Xl[r*XST + c4 + 3] = tf32f(v.w - h3);
        }
    }

    float acc[8][4];
    #pragma unroll
    for (int i = 0; i < 8; i++)
        #pragma unroll
        for (int j = 0; j < 4; j++) acc[i][j] = 0.f;

    float4 wreg[4];
    #pragma unroll
    for (int r = 0; r < 4; r++)
        wreg[r] = *(const float4*)&Wsk[wm[r]*CC + wk4[r]];

    for (int kc = 0; kc < 4; kc++) {
        __syncthreads();
        #pragma unroll
        for (int r = 0; r < 4; r++) {
            float h0 = tf32f(wreg[r].x), h1 = tf32f(wreg[r].y);
            float h2 = tf32f(wreg[r].z), h3 = tf32f(wreg[r].w);
            Wh[wm[r]*WST + wk4[r] + 0] = h0;  Wl[wm[r]*WST + wk4[r] + 0] = tf32f(wreg[r].x - h0);
            Wh[wm[r]*WST + wk4[r] + 1] = h1;  Wl[wm[r]*WST + wk4[r] + 1] = tf32f(wreg[r].y - h1);
            Wh[wm[r]*WST + wk4[r] + 2] = h2;  Wl[wm[r]*WST + wk4[r] + 2] = tf32f(wreg[r].z - h2);
            Wh[wm[r]*WST + wk4[r] + 3] = h3;  Wl[wm[r]*WST + wk4[r] + 3] = tf32f(wreg[r].w - h3);
        }
        __syncthreads();
        if (kc < 3) {
            #pragma unroll
            for (int r = 0; r < 4; r++)
                wreg[r] = *(const float4*)&Wsk[wm[r]*CC + (kc + 1)*32 + wk4[r]];
        }
        #pragma unroll
        for (int ks = 0; ks < 4; ks++) {
            int kk = ks * 8;
            uint32_t ah[4], al[4];
            ah[0] = __float_as_uint(Wh[(m0 + gid    )*WST + kk + tig    ]);
            ah[1] = __float_as_uint(Wh[(m0 + gid + 8)*WST + kk + tig    ]);
            ah[2] = __float_as_uint(Wh[(m0 + gid    )*WST + kk + tig + 4]);
            ah[3] = __float_as_uint(Wh[(m0 + gid + 8)*WST + kk + tig + 4]);
            al[0] = __float_as_uint(Wl[(m0 + gid    )*WST + kk + tig    ]);
            al[1] = __float_as_uint(Wl[(m0 + gid + 8)*WST + kk + tig    ]);
            al[2] = __float_as_uint(Wl[(m0 + gid    )*WST + kk + tig + 4]);
            al[3] = __float_as_uint(Wl[(m0 + gid + 8)*WST + kk + tig + 4]);
            #pragma unroll
            for (int nt = 0; nt < 8; nt++) {
                uint32_t bh0 = __float_as_uint(Xh[(kc*32 + kk + tig    )*XST + nt*8 + gid]);
                uint32_t bh1 = __float_as_uint(Xh[(kc*32 + kk + tig + 4)*XST + nt*8 + gid]);
                uint32_t bl0 = __float_as_uint(Xl[(kc*32 + kk + tig    )*XST + nt*8 + gid]);
                uint32_t bl1 = __float_as_uint(Xl[(kc*32 + kk + tig + 4)*XST + nt*8 + gid]);
                mma_tf32_k8(acc[nt], ah, bh0, bh1);
                mma_tf32_k8(acc[nt], ah, bl0, bl1);
                mma_tf32_k8(acc[nt], al, bh0, bh1);
            }
        }
    }
    #pragma unroll
    for (int nt = 0; nt < 8; nt++) {
        int n = n0 + nt*8 + 2*tig;
        float* o = out + (size_t)(b*CC)*NN;
        *(float2*)&o[(m0 + gid    )*NN + n] = make_float2(acc[nt][0], acc[nt][1]);
        *(float2*)&o[(m0 + gid + 8)*NN + n] = make_float2(acc[nt][2], acc[nt][3]);
    }
}

// ---------------------------------------------------------------------------
// flash attention (R13 config — best measured): fp16 m16n8k16, 256 threads,
// 8 warps, warp owns 32 q rows (2 M-subtiles sharing K/V fragments).
// Vectorized uint4 staging, double-buffered smem, one barrier/kt.
// lsum via HADD2 on P fragments.
// ---------------------------------------------------------------------------
#define KPST 20    // u32 stride (80B rows): LDSM conflict-free
#define VPST 36    // u32 stride (144B rows)
#define KBUF (64*KPST)
#define VBUF (32*VPST)

__global__ __launch_bounds__(256, 1) void flash_kernel(float* __restrict__ out)
{
    __shared__ __align__(16) uint32_t Kp[2*KBUF];    // [buf][key][dpair]
    __shared__ __align__(16) uint32_t Vp[2*VBUF];    // [buf][d][jpair]

    int tid = threadIdx.x;
    int w = tid >> 5, lane = tid & 31, gid = lane >> 2, tig = lane & 3;
    int qt = blockIdx.x, h = blockIdx.y, b = blockIdx.z;
    int q0 = qt * 256;

    const float*    Qf = g_Qf + (size_t)(b*CC + h*32)*NN + q0;
    const uint32_t* Kt = g_Kt + ((size_t)(b*HH + h)*NN)*16;
    const uint32_t* Vu = g_Vb + (size_t)(b*CC + h*32)*(NN/2);

    // staging indices: one 16B chunk each for K and V per thread
    int skey = tid >> 2, sq = tid & 3;            // K: key row, 16B quarter
    int svd  = tid >> 3, svq = tid & 7;           // V: d row, 16B eighth

    // ldmatrix per-thread base addresses (buffer 0)
    int lrow = lane & 7, lm = lane >> 3;
    uint32_t kp_b = smem_u32p(Kp), vp_b = smem_u32p(Vp);
    uint32_t kaddr0 = kp_b + (uint32_t)(lrow*(KPST*4) + (lm >> 1)*32 + (lm & 1)*16);
    uint32_t vaddr0 = vp_b + (uint32_t)(((lm >> 1)*8 + lrow)*(VPST*4) + (lm & 1)*16);

    // Q fragments (fp16, persist all tiles): 2 subtiles of 16 rows
    uint32_t qa[2][2][4];
    #pragma unroll
    for (int st = 0; st < 2; st++) {
        int r0 = w*32 + st*16 + gid;
        #pragma unroll
        for (int ks = 0; ks < 2; ks++) {
            int d = ks*16 + 2*tig;
            qa[st][ks][0] = packh(Qf[(d    )*NN + r0    ], Qf[(d + 1)*NN + r0    ]);
            qa[st][ks][1] = packh(Qf[(d    )*NN + r0 + 8], Qf[(d + 1)*NN + r0 + 8]);
            qa[st][ks][2] = packh(Qf[(d + 8)*NN + r0    ], Qf[(d + 9)*NN + r0    ]);
            qa[st][ks][3] = packh(Qf[(d + 8)*NN + r0 + 8], Qf[(d + 9)*NN + r0 + 8]);
        }
    }

    float o[2][4][4];
    #pragma unroll
    for (int st = 0; st < 2; st++)
        #pragma unroll
        for (int i = 0; i < 4; i++)
            #pragma unroll
            for (int j = 0; j < 4; j++) o[st][i][j] = 0.f;
    float lsum[2][2] = {{0.f, 0.f}, {0.f, 0.f}};

    // stage tile 0 into buffer 0 (vector copies)
    {
        uint4 kv = *(const uint4*)&Kt[(size_t)skey*16 + sq*4];
        uint4 vv = *(const uint4*)&Vu[(size_t)svd*(NN/2) + svq*4];
        *(uint4*)&Kp[skey*KPST + sq*4] = kv;
        *(uint4*)&Vp[svd*VPST + svq*4] = vv;
    }
    __syncthreads();

    for (int kt = 0; kt < 64; kt++) {
        int cur = kt & 1, nxt = cur ^ 1;
        uint32_t kaddr = kaddr0 + (uint32_t)(cur * (KBUF*4));
        uint32_t vaddr = vaddr0 + (uint32_t)(cur * (VBUF*4));

        // prefetch next tile into registers
        uint4 nK, nV;
        if (kt < 63) {
            nK = *(const uint4*)&Kt[(size_t)((kt + 1)*64 + skey)*16 + sq*4];
            nV = *(const uint4*)&Vu[(size_t)svd*(NN/2) + (kt + 1)*32 + svq*4];
        }

        // S = Q @ K^T per n-tile, both subtiles share K fragments
        uint32_t pa[2][4][4];
        uint32_t hs[2][2] = {{0u, 0u}, {0u, 0u}};   // f16x2 partial row sums
        #pragma unroll
        for (int nt = 0; nt < 8; nt++) {
            uint32_t k0, k1, k2, k3;
            ldsm_x4(k0, k1, k2, k3, kaddr + (uint32_t)(nt*8*KPST*4));
            #pragma unroll
            for (int st = 0; st < 2; st++) {
                float sv[4] = {0.f, 0.f, 0.f, 0.f};
                mma_f16_k16(sv, qa[st][0], k0, k1);
                mma_f16_k16(sv, qa[st][1], k2, k3);
                uint32_t p01 = ex2h(packh(sv[0], sv[1]));
                uint32_t p23 = ex2h(packh(sv[2], sv[3]));
                hs[st][0] = hadd2(hs[st][0], p01);
                hs[st][1] = hadd2(hs[st][1], p23);
                pa[st][nt >> 1][(nt & 1)*2    ] = p01;
                pa[st][nt >> 1][(nt & 1)*2 + 1] = p23;
            }
        }
        // fold per-kt f16x2 sums into fp32
        #pragma unroll
        for (int st = 0; st < 2; st++) {
            float2 t0 = __half22float2(*(const __half2*)&hs[st][0]);
            float2 t1 = __half22float2(*(const __half2*)&hs[st][1]);
            lsum[st][0] += t0.x + t0.y;
            lsum[st][1] += t1.x + t1.y;
        }

        // O += P @ V (V fragments shared by both subtiles)
        #pragma unroll
        for (int g = 0; g < 4; g++) {
            uint32_t vb0[4], vb1[4];
            ldsm_x4(vb0[0], vb0[1], vb0[2], vb0[3], vaddr + (uint32_t)(g*32));
            ldsm_x4(vb1[0], vb1[1], vb1[2], vb1[3], vaddr + (uint32_t)(16*VPST*4 + g*32));
            #pragma unroll
            for (int st = 0; st < 2; st++) {
                mma_f16_k16(o[st][0], pa[st][g], vb0[0], vb0[1]);
                mma_f16_k16(o[st][1], pa[st][g], vb0[2], vb0[3]);
                mma_f16_k16(o[st][2], pa[st][g], vb1[0], vb1[1]);
                mma_f16_k16(o[st][3], pa[st][g], vb1[2], vb1[3]);
            }
        }

        // store prefetched tile into the OTHER buffer; single barrier per kt
        if (kt < 63) {
            *(uint4*)&Kp[nxt*KBUF + skey*KPST + sq*4] = nK;
            *(uint4*)&Vp[nxt*VBUF + svd*VPST + svq*4] = nV;
            __syncthreads();
        }
    }

    // epilogue: reduce lsum across row group, divide, add into out
    #pragma unroll
    for (int st = 0; st < 2; st++) {
        #pragma unroll
        for (int half = 0; half < 2; half++) {
            lsum[st][half] += __shfl_xor_sync(0xffffffffu, lsum[st][half], 1);
            lsum[st][half] += __shfl_xor_sync(0xffffffffu, lsum[st][half], 2);
        }
    }
    #pragma unroll
    for (int st = 0; st < 2; st++) {
        int r0 = w*32 + st*16 + gid;
        float inv0 = 1.f / lsum[st][0], inv1 = 1.f / lsum[st][1];
        #pragma unroll
        for (int nt = 0; nt < 4; nt++) {
            int d = nt*8 + 2*tig;
            float* base = out + (size_t)(b*CC + h*32)*NN + q0;
            base[(d    )*NN + r0    ] += o[st][nt][0] * inv0;
            base[(d + 1)*NN + r0    ] += o[st][nt][1] * inv0;
            base[(d    )*NN + r0 + 8] += o[st][nt][2] * inv1;
            base[(d + 1)*NN + r0 + 8] += o[st][nt][3] * inv1;
        }
    }
}

extern "C" void kernel_launch(void* const* d_in, const int* in_sizes, int n_in,
                              void* d_out, int out_size)
{
    const float* pcd_up = (const float*)d_in[0];
    const float* sel    = (const float*)d_in[1];
    const float* drop   = (const float*)d_in[2];
    // d_in[3] = pcd_up_xyz, unused by the reference math
    const float* Wq     = (const float*)d_in[4];
    const float* Wk     = (const float*)d_in[5];
    const float* Wv     = (const float*)d_in[6];
    const float* Wsk    = (const float*)d_in[7];
    const void*  idxs   = d_in[8];
    const void*  idxd   = d_in[9];
    float* out = (float*)d_out;

    static bool attr_set = false;
    if (!attr_set) {
        cudaFuncSetAttribute(proj_kernel, cudaFuncAttributeMaxDynamicSharedMemorySize,
                             PSMEM);
        attr_set = true;
    }

    prep_kernel<<<(2*BB*NSS)/256, 256>>>(idxs, idxd);
    proj_kernel<<<dim3(NN/64, BB), 256, PSMEM>>>(pcd_up, sel, drop, Wq, Wk, Wv, Wsk, out);
    flash_kernel<<<dim3(NN/256, HH, BB), 256>>>(out);
}